// round 7
// baseline (speedup 1.0000x reference)
#include <cuda_runtime.h>
#include <cstdint>

#define BATCH 2048
#define TLEN  4096
#define ALPHA_C 0.95f
#define THETA_C 0.05f

// scan geometry
#define ROWS_PB 64
#define SEG     512
#define NSEG    (TLEN / SEG)        // 8
#define WU      384                 // warm-up steps (alpha^384 ~ 3e-9)
#define TILE    32
#define TSTRIDE 36                  // 144B row stride; %32==4 -> LDS.128 conflict-free

#define CP_ASYNC16(dst, src) \
    asm volatile("cp.async.cg.shared.global [%0], [%1], 16;" :: "r"(dst), "l"(src))
#define CP_COMMIT() asm volatile("cp.async.commit_group;")

__device__ __forceinline__ uint32_t smem_u32(const void* p) {
    return (uint32_t)__cvta_generic_to_shared(p);
}

// ---------------------------------------------------------------------------
// Kernel 1: causal convs — identical math to rounds 4-6 (u bitwise same),
// now sliced in t via tbase.
// ---------------------------------------------------------------------------
__global__ void __launch_bounds__(256) conv_kernel(
    const float* __restrict__ x,
    const float* __restrict__ w8,
    const float* __restrict__ w16,
    const float* __restrict__ w32,
    float* __restrict__ u,
    int tbase)
{
    __shared__ float xs[32][97];
    __shared__ float sw8[8], sw16[16], sw32[32];

    const int tx  = threadIdx.x;
    const int ty  = threadIdx.y;
    const int tid = ty * 8 + tx;
    const int t0  = tbase + blockIdx.x * 64;
    const int b0  = blockIdx.y * 32;
    const int warp = tid >> 5;
    const int lane = tid & 31;

    if (tid < 8)       sw8[tid]       = w8[tid];
    else if (tid < 24) sw16[tid - 8]  = w16[tid - 8];
    else if (tid < 56) sw32[tid - 24] = w32[tid - 24];

    {
        const int r0 = warp << 2;
#pragma unroll
        for (int rr = 0; rr < 4; rr++) {
            const float* xrow = x + (size_t)(b0 + r0 + rr) * TLEN;
#pragma unroll
            for (int seg = 0; seg < 3; seg++) {
                int i = (seg << 5) + lane;
                int t = t0 - 32 + i;
                xs[r0 + rr][i] = (t >= 0) ? xrow[t] : 0.0f;
            }
        }
    }
    __syncthreads();

    float xw[39];
#pragma unroll
    for (int j = 0; j < 39; j++) xw[j] = xs[ty][(tx << 3) + 1 + j];

    float a8[8], a16[8], a32[8];
#pragma unroll
    for (int i = 0; i < 8; i++) { a8[i] = 0.f; a16[i] = 0.f; a32[i] = 0.f; }

#pragma unroll
    for (int j = 0; j < 32; j++) {
        float w = sw32[j];
#pragma unroll
        for (int i = 0; i < 8; i++) a32[i] = fmaf(w, xw[i + j], a32[i]);
    }
#pragma unroll
    for (int j = 0; j < 16; j++) {
        float w = sw16[j];
#pragma unroll
        for (int i = 0; i < 8; i++) a16[i] = fmaf(w, xw[16 + i + j], a16[i]);
    }
#pragma unroll
    for (int j = 0; j < 8; j++) {
        float w = sw8[j];
#pragma unroll
        for (int i = 0; i < 8; i++) a8[i] = fmaf(w, xw[24 + i + j], a8[i]);
    }

    float* ub = u + ((size_t)(b0 + ty) * 3) * TLEN + t0 + (tx << 3);
    reinterpret_cast<float4*>(ub + 0 * TLEN)[0] = make_float4(a8[0],  a8[1],  a8[2],  a8[3]);
    reinterpret_cast<float4*>(ub + 0 * TLEN)[1] = make_float4(a8[4],  a8[5],  a8[6],  a8[7]);
    reinterpret_cast<float4*>(ub + 1 * TLEN)[0] = make_float4(a16[0], a16[1], a16[2], a16[3]);
    reinterpret_cast<float4*>(ub + 1 * TLEN)[1] = make_float4(a16[4], a16[5], a16[6], a16[7]);
    reinterpret_cast<float4*>(ub + 2 * TLEN)[0] = make_float4(a32[0], a32[1], a32[2], a32[3]);
    reinterpret_cast<float4*>(ub + 2 * TLEN)[1] = make_float4(a32[4], a32[5], a32[6], a32[7]);
}

// ---------------------------------------------------------------------------
// LIF + WTA step — decision logic IDENTICAL to validated rounds 1-6.
// ---------------------------------------------------------------------------
__device__ __forceinline__ void lif_step_s(float u0, float u1, float u2,
                                           float& v0, float& v1, float& v2,
                                           float& s0, float& s1, float& s2)
{
    float w0 = fmaf(ALPHA_C, v0, u0);
    float w1 = fmaf(ALPHA_C, v1, u1);
    float w2 = fmaf(ALPHA_C, v2, u2);
    float m0 = w0 - THETA_C;
    float m1 = w1 - THETA_C;
    float m2 = w2 - THETA_C;
    float best = fmaxf(m0, fmaxf(m1, m2));
    bool fire = (best >= 0.0f);
    bool t0 = (m0 == best);
    bool t1 = (m1 == best);
    bool e0 = fire && t0;
    bool e1 = fire && t1 && !t0;
    bool e2 = fire && !t0 && !t1;
    s0 = e0 ? 1.0f : 0.0f;
    s1 = e1 ? 1.0f : 0.0f;
    s2 = e2 ? 1.0f : 0.0f;
    v0 = e0 ? m0 : w0;
    v1 = e1 ? m1 : w1;
    v2 = e2 ? m2 : w2;
}

// ---------------------------------------------------------------------------
// Kernel 2: fused LIF scan. blockDim 128: threads 0-63 compute (one row each);
// ALL 128 threads stage (cp.async) and store out -> issue on all 4 SMSPs.
// One segment per launch (seg param) so it can overlap conv slices.
// ---------------------------------------------------------------------------
__global__ void __launch_bounds__(128, 2) scan_fused(
    const float* __restrict__ u, float* __restrict__ s, int seg)
{
    __shared__ float buf[2][3][ROWS_PB][TSTRIDE];

    const int tid = threadIdx.x;              // 0..127
    const int b0  = blockIdx.x * ROWS_PB;

    const int t_out0   = seg * SEG;
    const int t_begin  = (seg == 0) ? 0 : (t_out0 - WU);
    const int ntiles   = (t_out0 + SEG - t_begin) / TILE;   // 16 or 28
    const int wu_tiles = (t_out0 - t_begin) / TILE;         // 0 or 12

    // staging tasks: 1536 per tile (16B each); 12 per thread
    // p = tid + 128*i -> k = p>>9, row = (p>>3)&63, f4 = p&7

    {
        int tt = t_begin;
#pragma unroll
        for (int i = 0; i < 12; i++) {
            int p = tid + (i << 7);
            int k = p >> 9, row = (p >> 3) & 63, f4 = p & 7;
            uint32_t dst = smem_u32(&buf[0][k][row][f4 << 2]);
            const float* src = u + ((size_t)(b0 + row) * 3 + k) * TLEN + tt + (f4 << 2);
            CP_ASYNC16(dst, src);
        }
        CP_COMMIT();
    }

    float v0 = 0.f, v1 = 0.f, v2 = 0.f;

#pragma unroll 1
    for (int ti = 0; ti < ntiles; ti++) {
        const int cur = ti & 1;
        const bool has_next = (ti + 1 < ntiles);
        const bool emit = (ti >= wu_tiles);

        if (has_next) {
            int tt = t_begin + (ti + 1) * TILE;
#pragma unroll
            for (int i = 0; i < 12; i++) {
                int p = tid + (i << 7);
                int k = p >> 9, row = (p >> 3) & 63, f4 = p & 7;
                uint32_t dst = smem_u32(&buf[cur ^ 1][k][row][f4 << 2]);
                const float* src = u + ((size_t)(b0 + row) * 3 + k) * TLEN + tt + (f4 << 2);
                CP_ASYNC16(dst, src);
            }
            CP_COMMIT();
            asm volatile("cp.async.wait_group 1;");
        } else {
            asm volatile("cp.async.wait_group 0;");
        }
        __syncthreads();

        // compute 32 steps; threads 0-63 own one row each
        if (tid < ROWS_PB) {
            if (emit) {
#pragma unroll
                for (int t4 = 0; t4 < 8; t4++) {
                    float4 c0 = *reinterpret_cast<float4*>(&buf[cur][0][tid][t4 << 2]);
                    float4 c1 = *reinterpret_cast<float4*>(&buf[cur][1][tid][t4 << 2]);
                    float4 c2 = *reinterpret_cast<float4*>(&buf[cur][2][tid][t4 << 2]);
                    float4 o0, o1, o2;
                    lif_step_s(c0.x, c1.x, c2.x, v0, v1, v2, o0.x, o1.x, o2.x);
                    lif_step_s(c0.y, c1.y, c2.y, v0, v1, v2, o0.y, o1.y, o2.y);
                    lif_step_s(c0.z, c1.z, c2.z, v0, v1, v2, o0.z, o1.z, o2.z);
                    lif_step_s(c0.w, c1.w, c2.w, v0, v1, v2, o0.w, o1.w, o2.w);
                    *reinterpret_cast<float4*>(&buf[cur][0][tid][t4 << 2]) = o0;
                    *reinterpret_cast<float4*>(&buf[cur][1][tid][t4 << 2]) = o1;
                    *reinterpret_cast<float4*>(&buf[cur][2][tid][t4 << 2]) = o2;
                }
            } else {
#pragma unroll
                for (int t4 = 0; t4 < 8; t4++) {
                    float4 c0 = *reinterpret_cast<float4*>(&buf[cur][0][tid][t4 << 2]);
                    float4 c1 = *reinterpret_cast<float4*>(&buf[cur][1][tid][t4 << 2]);
                    float4 c2 = *reinterpret_cast<float4*>(&buf[cur][2][tid][t4 << 2]);
                    float4 o0, o1, o2;
                    lif_step_s(c0.x, c1.x, c2.x, v0, v1, v2, o0.x, o1.x, o2.x);
                    lif_step_s(c0.y, c1.y, c2.y, v0, v1, v2, o0.y, o1.y, o2.y);
                    lif_step_s(c0.z, c1.z, c2.z, v0, v1, v2, o0.z, o1.z, o2.z);
                    lif_step_s(c0.w, c1.w, c2.w, v0, v1, v2, o0.w, o1.w, o2.w);
                }
            }
        }

        if (emit) {
            __syncthreads();     // spikes visible to all threads
            int tt = t_begin + ti * TILE;
#pragma unroll
            for (int i = 0; i < 12; i++) {
                int p = tid + (i << 7);
                int k = p >> 9, row = (p >> 3) & 63, f4 = p & 7;
                float4 o = *reinterpret_cast<float4*>(&buf[cur][k][row][f4 << 2]);
                *reinterpret_cast<float4*>(
                    s + ((size_t)(b0 + row) * 3 + k) * TLEN + tt + (f4 << 2)) = o;
            }
        }
        __syncthreads();         // buf[cur] free for re-staging
    }
}

// ---------------------------------------------------------------------------
// Launch: conv sliced into NSEG t-ranges on the main stream; each scan segment
// forked onto a side stream after its conv slice (event fork/join — all
// graph-capturable; stream/events are static HOST objects, no device memory).
// ---------------------------------------------------------------------------
extern "C" void kernel_launch(void* const* d_in, const int* in_sizes, int n_in,
                              void* d_out, int out_size)
{
    const float* x   = (const float*)d_in[0];
    const float* w8  = (const float*)d_in[1];
    const float* w16 = (const float*)d_in[2];
    const float* w32 = (const float*)d_in[3];

    float* u = (float*)d_out;
    float* s = u + (size_t)BATCH * 3 * TLEN;

    static cudaStream_t s1 = nullptr;
    static cudaEvent_t  ev[NSEG];
    static cudaEvent_t  evj = nullptr;
    if (s1 == nullptr) {
        cudaStreamCreateWithFlags(&s1, cudaStreamNonBlocking);
        for (int i = 0; i < NSEG; i++)
            cudaEventCreateWithFlags(&ev[i], cudaEventDisableTiming);
        cudaEventCreateWithFlags(&evj, cudaEventDisableTiming);
    }

    for (int i = 0; i < NSEG; i++) {
        conv_kernel<<<dim3(SEG / 64, BATCH / 32), dim3(8, 32)>>>(
            x, w8, w16, w32, u, i * SEG);
        cudaEventRecord(ev[i], 0);
        cudaStreamWaitEvent(s1, ev[i], 0);
        scan_fused<<<BATCH / ROWS_PB, 128, 0, s1>>>(u, s, i);
    }
    cudaEventRecord(evj, s1);
    cudaStreamWaitEvent(0, evj, 0);
}

// round 8
// speedup vs baseline: 2.3560x; 2.3560x over previous
#include <cuda_runtime.h>
#include <cstdint>

#define BATCH 2048
#define TLEN  4096
#define ALPHA_C 0.95f
#define THETA_C 0.05f

// scan geometry
#define ROWS_PB 128                 // batch rows per block (2 per compute thread)
#define SEG     512
#define NSEG    (TLEN / SEG)        // 8
#define WU      384                 // warm-up steps (alpha^384 ~ 3e-9)
#define TILE    32
#define TSTRIDE 36                  // 144B row stride; conflict-free LDS.128

#define CP_ASYNC16(dst, src) \
    asm volatile("cp.async.cg.shared.global [%0], [%1], 16;" :: "r"(dst), "l"(src))
#define CP_COMMIT() asm volatile("cp.async.commit_group;")

#define PACK2(out, lo, hi) \
    asm("mov.b64 %0, {%1, %2};" : "=l"(out) : "f"(lo), "f"(hi))
#define UNPACK2(lo, hi, in) \
    asm("mov.b64 {%0, %1}, %2;" : "=f"(lo), "=f"(hi) : "l"(in))
#define FMA2(d, a, b, c) \
    asm("fma.rn.f32x2 %0, %1, %2, %3;" : "=l"(d) : "l"(a), "l"(b), "l"(c))

__device__ __forceinline__ uint32_t smem_u32(const void* p) {
    return (uint32_t)__cvta_generic_to_shared(p);
}

// ---------------------------------------------------------------------------
// Kernel 1: causal convs with packed f32x2 FMA. Per-lane IEEE fp32 FMA with
// identical tap order -> u bitwise identical to rounds 4-6.
// ---------------------------------------------------------------------------
__global__ void __launch_bounds__(256) conv_kernel(
    const float* __restrict__ x,
    const float* __restrict__ w8,
    const float* __restrict__ w16,
    const float* __restrict__ w32,
    float* __restrict__ u)
{
    __shared__ float xs[32][97];
    __shared__ float sw8[8], sw16[16], sw32[32];

    const int tx  = threadIdx.x;               // 0..7
    const int ty  = threadIdx.y;               // 0..31
    const int tid = ty * 8 + tx;
    const int t0  = blockIdx.x * 64;
    const int b0  = blockIdx.y * 32;
    const int warp = tid >> 5;
    const int lane = tid & 31;

    if (tid < 8)       sw8[tid]       = w8[tid];
    else if (tid < 24) sw16[tid - 8]  = w16[tid - 8];
    else if (tid < 56) sw32[tid - 24] = w32[tid - 24];

    {
        const int r0 = warp << 2;
#pragma unroll
        for (int rr = 0; rr < 4; rr++) {
            const float* xrow = x + (size_t)(b0 + r0 + rr) * TLEN;
#pragma unroll
            for (int seg = 0; seg < 3; seg++) {
                int i = (seg << 5) + lane;
                int t = t0 - 32 + i;
                xs[r0 + rr][i] = (t >= 0) ? xrow[t] : 0.0f;
            }
        }
    }
    __syncthreads();

    // window xw[j] = x[row, tbase - 31 + j], j = 0..38
    float xw[39];
#pragma unroll
    for (int j = 0; j < 39; j++) xw[j] = xs[ty][(tx << 3) + 1 + j];

    // packed sliding pairs xp[j] = (xw[j], xw[j+1])
    unsigned long long xp[38];
#pragma unroll
    for (int j = 0; j < 38; j++) PACK2(xp[j], xw[j], xw[j + 1]);

    unsigned long long A8[4], A16[4], A32[4];
#pragma unroll
    for (int p = 0; p < 4; p++) { A8[p] = 0ULL; A16[p] = 0ULL; A32[p] = 0ULL; }

#pragma unroll
    for (int j = 0; j < 32; j++) {
        float w = sw32[j];
        unsigned long long w2; PACK2(w2, w, w);
#pragma unroll
        for (int p = 0; p < 4; p++) FMA2(A32[p], xp[(p << 1) + j], w2, A32[p]);
    }
#pragma unroll
    for (int j = 0; j < 16; j++) {
        float w = sw16[j];
        unsigned long long w2; PACK2(w2, w, w);
#pragma unroll
        for (int p = 0; p < 4; p++) FMA2(A16[p], xp[16 + (p << 1) + j], w2, A16[p]);
    }
#pragma unroll
    for (int j = 0; j < 8; j++) {
        float w = sw8[j];
        unsigned long long w2; PACK2(w2, w, w);
#pragma unroll
        for (int p = 0; p < 4; p++) FMA2(A8[p], xp[24 + (p << 1) + j], w2, A8[p]);
    }

    float a8[8], a16[8], a32[8];
#pragma unroll
    for (int p = 0; p < 4; p++) {
        UNPACK2(a8[2 * p],  a8[2 * p + 1],  A8[p]);
        UNPACK2(a16[2 * p], a16[2 * p + 1], A16[p]);
        UNPACK2(a32[2 * p], a32[2 * p + 1], A32[p]);
    }

    float* ub = u + ((size_t)(b0 + ty) * 3) * TLEN + t0 + (tx << 3);
    reinterpret_cast<float4*>(ub + 0 * TLEN)[0] = make_float4(a8[0],  a8[1],  a8[2],  a8[3]);
    reinterpret_cast<float4*>(ub + 0 * TLEN)[1] = make_float4(a8[4],  a8[5],  a8[6],  a8[7]);
    reinterpret_cast<float4*>(ub + 1 * TLEN)[0] = make_float4(a16[0], a16[1], a16[2], a16[3]);
    reinterpret_cast<float4*>(ub + 1 * TLEN)[1] = make_float4(a16[4], a16[5], a16[6], a16[7]);
    reinterpret_cast<float4*>(ub + 2 * TLEN)[0] = make_float4(a32[0], a32[1], a32[2], a32[3]);
    reinterpret_cast<float4*>(ub + 2 * TLEN)[1] = make_float4(a32[4], a32[5], a32[6], a32[7]);
}

// ---------------------------------------------------------------------------
// LIF + WTA step — decision logic IDENTICAL to validated rounds 1-7.
// ---------------------------------------------------------------------------
__device__ __forceinline__ void lif_step_s(float u0, float u1, float u2,
                                           float& v0, float& v1, float& v2,
                                           float& s0, float& s1, float& s2)
{
    float w0 = fmaf(ALPHA_C, v0, u0);
    float w1 = fmaf(ALPHA_C, v1, u1);
    float w2 = fmaf(ALPHA_C, v2, u2);
    float m0 = w0 - THETA_C;
    float m1 = w1 - THETA_C;
    float m2 = w2 - THETA_C;
    float best = fmaxf(m0, fmaxf(m1, m2));
    bool fire = (best >= 0.0f);
    bool t0 = (m0 == best);
    bool t1 = (m1 == best);
    bool e0 = fire && t0;
    bool e1 = fire && t1 && !t0;
    bool e2 = fire && !t0 && !t1;
    s0 = e0 ? 1.0f : 0.0f;
    s1 = e1 ? 1.0f : 0.0f;
    s2 = e2 ? 1.0f : 0.0f;
    v0 = e0 ? m0 : w0;
    v1 = e1 ? m1 : w1;
    v2 = e2 ? m2 : w2;
}

// ---------------------------------------------------------------------------
// Kernel 2: fused LIF scan, ILP=2. Block = 128 threads, 128 rows.
// Threads 0-63 each scan TWO rows (tid, tid+64) with interleaved chains;
// all 128 threads stage (cp.async) and store out.
// smem (dynamic): buf[2][3][128][TSTRIDE]
// ---------------------------------------------------------------------------
#define BUF(slot, k, row, t) \
    sbuf[((((slot) * 3 + (k)) * ROWS_PB + (row)) * TSTRIDE) + (t)]

__global__ void __launch_bounds__(128, 1) scan_fused(
    const float* __restrict__ u, float* __restrict__ s)
{
    extern __shared__ float sbuf[];

    const int tid = threadIdx.x;              // 0..127
    const int b0  = blockIdx.x * ROWS_PB;
    const int seg = blockIdx.y;

    const int t_out0   = seg * SEG;
    const int t_begin  = (seg == 0) ? 0 : (t_out0 - WU);
    const int ntiles   = (t_out0 + SEG - t_begin) / TILE;   // 16 or 28
    const int wu_tiles = (t_out0 - t_begin) / TILE;         // 0 or 12

    // staging: 3*128*8 = 3072 16B tasks per tile, 24 per thread
    // p = tid + 128*i -> k = p>>10, row = (p>>3)&127, f4 = p&7

    {
        int tt = t_begin;
#pragma unroll
        for (int i = 0; i < 24; i++) {
            int p = tid + (i << 7);
            int k = p >> 10, row = (p >> 3) & 127, f4 = p & 7;
            uint32_t dst = smem_u32(&BUF(0, k, row, f4 << 2));
            const float* src = u + ((size_t)(b0 + row) * 3 + k) * TLEN + tt + (f4 << 2);
            CP_ASYNC16(dst, src);
        }
        CP_COMMIT();
    }

    float va0 = 0.f, va1 = 0.f, va2 = 0.f;    // chain A: row tid
    float vb0 = 0.f, vb1 = 0.f, vb2 = 0.f;    // chain B: row tid+64

#pragma unroll 1
    for (int ti = 0; ti < ntiles; ti++) {
        const int cur = ti & 1;
        const bool has_next = (ti + 1 < ntiles);
        const bool emit = (ti >= wu_tiles);

        if (has_next) {
            int tt = t_begin + (ti + 1) * TILE;
#pragma unroll
            for (int i = 0; i < 24; i++) {
                int p = tid + (i << 7);
                int k = p >> 10, row = (p >> 3) & 127, f4 = p & 7;
                uint32_t dst = smem_u32(&BUF(cur ^ 1, k, row, f4 << 2));
                const float* src = u + ((size_t)(b0 + row) * 3 + k) * TLEN + tt + (f4 << 2);
                CP_ASYNC16(dst, src);
            }
            CP_COMMIT();
            asm volatile("cp.async.wait_group 1;");
        } else {
            asm volatile("cp.async.wait_group 0;");
        }
        __syncthreads();

        if (tid < 64) {
            const int rA = tid, rB = tid + 64;
#pragma unroll
            for (int t4 = 0; t4 < 8; t4++) {
                float4 cA0 = *reinterpret_cast<float4*>(&BUF(cur, 0, rA, t4 << 2));
                float4 cA1 = *reinterpret_cast<float4*>(&BUF(cur, 1, rA, t4 << 2));
                float4 cA2 = *reinterpret_cast<float4*>(&BUF(cur, 2, rA, t4 << 2));
                float4 cB0 = *reinterpret_cast<float4*>(&BUF(cur, 0, rB, t4 << 2));
                float4 cB1 = *reinterpret_cast<float4*>(&BUF(cur, 1, rB, t4 << 2));
                float4 cB2 = *reinterpret_cast<float4*>(&BUF(cur, 2, rB, t4 << 2));
                float4 oA0, oA1, oA2, oB0, oB1, oB2;
                // interleaved independent chains (ILP=2)
                lif_step_s(cA0.x, cA1.x, cA2.x, va0, va1, va2, oA0.x, oA1.x, oA2.x);
                lif_step_s(cB0.x, cB1.x, cB2.x, vb0, vb1, vb2, oB0.x, oB1.x, oB2.x);
                lif_step_s(cA0.y, cA1.y, cA2.y, va0, va1, va2, oA0.y, oA1.y, oA2.y);
                lif_step_s(cB0.y, cB1.y, cB2.y, vb0, vb1, vb2, oB0.y, oB1.y, oB2.y);
                lif_step_s(cA0.z, cA1.z, cA2.z, va0, va1, va2, oA0.z, oA1.z, oA2.z);
                lif_step_s(cB0.z, cB1.z, cB2.z, vb0, vb1, vb2, oB0.z, oB1.z, oB2.z);
                lif_step_s(cA0.w, cA1.w, cA2.w, va0, va1, va2, oA0.w, oA1.w, oA2.w);
                lif_step_s(cB0.w, cB1.w, cB2.w, vb0, vb1, vb2, oB0.w, oB1.w, oB2.w);
                if (emit) {
                    *reinterpret_cast<float4*>(&BUF(cur, 0, rA, t4 << 2)) = oA0;
                    *reinterpret_cast<float4*>(&BUF(cur, 1, rA, t4 << 2)) = oA1;
                    *reinterpret_cast<float4*>(&BUF(cur, 2, rA, t4 << 2)) = oA2;
                    *reinterpret_cast<float4*>(&BUF(cur, 0, rB, t4 << 2)) = oB0;
                    *reinterpret_cast<float4*>(&BUF(cur, 1, rB, t4 << 2)) = oB1;
                    *reinterpret_cast<float4*>(&BUF(cur, 2, rB, t4 << 2)) = oB2;
                }
            }
        }

        if (emit) {
            __syncthreads();     // spikes visible to all threads
            int tt = t_begin + ti * TILE;
#pragma unroll
            for (int i = 0; i < 24; i++) {
                int p = tid + (i << 7);
                int k = p >> 10, row = (p >> 3) & 127, f4 = p & 7;
                float4 o = *reinterpret_cast<float4*>(&BUF(cur, k, row, f4 << 2));
                *reinterpret_cast<float4*>(
                    s + ((size_t)(b0 + row) * 3 + k) * TLEN + tt + (f4 << 2)) = o;
            }
        }
        __syncthreads();         // buf[cur] free for re-staging
    }
}

// ---------------------------------------------------------------------------
extern "C" void kernel_launch(void* const* d_in, const int* in_sizes, int n_in,
                              void* d_out, int out_size)
{
    const float* x   = (const float*)d_in[0];
    const float* w8  = (const float*)d_in[1];
    const float* w16 = (const float*)d_in[2];
    const float* w32 = (const float*)d_in[3];

    float* u = (float*)d_out;
    float* s = u + (size_t)BATCH * 3 * TLEN;

    const int SMEM_SCAN = 2 * 3 * ROWS_PB * TSTRIDE * 4;   // 110592 bytes
    static bool attr_set = false;
    if (!attr_set) {
        cudaFuncSetAttribute(scan_fused,
            cudaFuncAttributeMaxDynamicSharedMemorySize, SMEM_SCAN);
        attr_set = true;
    }

    conv_kernel<<<dim3(TLEN / 64, BATCH / 32), dim3(8, 32)>>>(x, w8, w16, w32, u);
    scan_fused<<<dim3(BATCH / ROWS_PB, NSEG), 128, SMEM_SCAN>>>(u, s);
}

// round 9
// speedup vs baseline: 2.5414x; 1.0787x over previous
#include <cuda_runtime.h>
#include <cstdint>

#define BATCH 2048
#define TLEN  4096
#define ALPHA_C 0.95f
#define THETA_C 0.05f

#define ROWS_PB 128
#define SEG     256
#define NSEG    (TLEN / SEG)     // 16
#define WU      384              // warm-up steps (alpha^384 ~ 3e-9)
#define TILE    32
#define TS      36               // smem row stride in floats (144B, 16B-aligned)

#define CP_ASYNC16(dst, src) \
    asm volatile("cp.async.cg.shared.global [%0], [%1], 16;" :: "r"(dst), "l"(src))
#define CP_COMMIT() asm volatile("cp.async.commit_group;")

#define PACK2(out, lo, hi) \
    asm("mov.b64 %0, {%1, %2};" : "=l"(out) : "f"(lo), "f"(hi))
#define FMA2(d, a, b, c) \
    asm("fma.rn.f32x2 %0, %1, %2, %3;" : "=l"(d) : "l"(a), "l"(b), "l"(c))

__device__ __forceinline__ uint32_t smem_u32(const void* p) {
    return (uint32_t)__cvta_generic_to_shared(p);
}

// ---------------------------------------------------------------------------
// LIF + WTA step — decision logic IDENTICAL to validated rounds 1-8.
// ---------------------------------------------------------------------------
__device__ __forceinline__ void lif_step_s(float u0, float u1, float u2,
                                           float& v0, float& v1, float& v2,
                                           float& s0, float& s1, float& s2)
{
    float w0 = fmaf(ALPHA_C, v0, u0);
    float w1 = fmaf(ALPHA_C, v1, u1);
    float w2 = fmaf(ALPHA_C, v2, u2);
    float m0 = w0 - THETA_C;
    float m1 = w1 - THETA_C;
    float m2 = w2 - THETA_C;
    float best = fmaxf(m0, fmaxf(m1, m2));
    bool fire = (best >= 0.0f);
    bool t0 = (m0 == best);
    bool t1 = (m1 == best);
    bool e0 = fire && t0;
    bool e1 = fire && t1 && !t0;
    bool e2 = fire && !t0 && !t1;
    s0 = e0 ? 1.0f : 0.0f;
    s1 = e1 ? 1.0f : 0.0f;
    s2 = e2 ? 1.0f : 0.0f;
    v0 = e0 ? m0 : w0;
    v1 = e1 ? m1 : w1;
    v2 = e2 ? m2 : w2;
}

// ---------------------------------------------------------------------------
// Fused kernel: per block = 128 batch rows x one 256-t output segment.
// Per 32-t tile: cp.async x -> conv in registers (FFMA2 pairs, bitwise-
// identical tap order) -> STS u -> STG u (emit) -> LIF scan (own row) ->
// spikes in place -> STG s (emit). Warm-up tiles: conv+scan only, no stores.
// smem: wb (56 packed weight pairs) | xb[2][128][TS] | ub[3][128][TS]
// ---------------------------------------------------------------------------
__global__ void __launch_bounds__(128, 1) fused_kernel(
    const float* __restrict__ x,
    const float* __restrict__ w8,
    const float* __restrict__ w16,
    const float* __restrict__ w32,
    float* __restrict__ uo,
    float* __restrict__ so)
{
    extern __shared__ float sm[];
    unsigned long long* wb = reinterpret_cast<unsigned long long*>(sm);  // 56 ull
    float* xb = sm + 112;                       // [2][128][TS]
    float* ub = sm + 112 + 2 * 128 * TS;        // [3][128][TS]
    unsigned long long* ub64 = reinterpret_cast<unsigned long long*>(ub);

    const int tid = threadIdx.x;                // row within block
    const int b0  = blockIdx.x * ROWS_PB;
    const int seg = blockIdx.y;

    const int t_out0   = seg * SEG;
    const int t_begin  = (t_out0 >= WU) ? (t_out0 - WU) : 0;
    const int ntiles   = (t_out0 + SEG - t_begin) / TILE;   // 8 / 16 / 20
    const int wu_tiles = (t_out0 - t_begin) / TILE;         // 0 / 8 / 12

    // packed (w,w) weight pairs: [0..31]=w32, [32..47]=w16, [48..55]=w8
    if (tid < 56) {
        float w = (tid < 32) ? w32[tid] : (tid < 48 ? w16[tid - 32] : w8[tid - 48]);
        unsigned long long w2; PACK2(w2, w, w);
        wb[tid] = w2;
    }

    // prologue: halo (x[t_begin-32..-1]) -> slot 0, tile0 -> slot 1
    {
        const bool zh = (t_begin == 0);         // zero-pad left
#pragma unroll
        for (int i = 0; i < 8; i++) {
            int p = tid + (i << 7);
            int row = p >> 3, f4 = p & 7;
            float* dh = &xb[(0 * 128 + row) * TS + (f4 << 2)];
            float* d0 = &xb[(1 * 128 + row) * TS + (f4 << 2)];
            const float* s0 = x + (size_t)(b0 + row) * TLEN + t_begin + (f4 << 2);
            if (zh) *reinterpret_cast<float4*>(dh) = make_float4(0.f, 0.f, 0.f, 0.f);
            else    CP_ASYNC16(smem_u32(dh), s0 - 32);
            CP_ASYNC16(smem_u32(d0), s0);
        }
        CP_COMMIT();
        asm volatile("cp.async.wait_group 0;");
    }
    __syncthreads();

    // initial window pairs xp[m] = (xw[m], xw[m+1]), xw[i] = x[row, t_begin-31+i]
    unsigned long long xp[62];
    float xlast;
    {
        float h[32], f[32];
#pragma unroll
        for (int i = 0; i < 8; i++) {
            float4 a = *reinterpret_cast<const float4*>(&xb[(0 * 128 + tid) * TS + (i << 2)]);
            h[4 * i + 0] = a.x; h[4 * i + 1] = a.y; h[4 * i + 2] = a.z; h[4 * i + 3] = a.w;
            float4 b = *reinterpret_cast<const float4*>(&xb[(1 * 128 + tid) * TS + (i << 2)]);
            f[4 * i + 0] = b.x; f[4 * i + 1] = b.y; f[4 * i + 2] = b.z; f[4 * i + 3] = b.w;
        }
#pragma unroll
        for (int m = 0; m < 30; m++) PACK2(xp[m], h[m + 1], h[m + 2]);
        PACK2(xp[30], h[31], f[0]);
#pragma unroll
        for (int i = 0; i < 31; i++) PACK2(xp[31 + i], f[i], f[i + 1]);
        xlast = f[31];
    }

    float v0 = 0.f, v1 = 0.f, v2 = 0.f;

#pragma unroll 1
    for (int ti = 0; ti < ntiles; ti++) {
        const bool has_next = (ti + 1 < ntiles);
        const bool emit = (ti >= wu_tiles);
        const int t0 = t_begin + ti * TILE;

        // prefetch x tile ti+1 into slot (ti&1); tile t lives in slot (t+1)&1
        if (has_next) {
            int tt = t0 + TILE;
#pragma unroll
            for (int i = 0; i < 8; i++) {
                int p = tid + (i << 7);
                int row = p >> 3, f4 = p & 7;
                float* dst = &xb[((ti & 1) * 128 + row) * TS + (f4 << 2)];
                const float* src = x + (size_t)(b0 + row) * TLEN + tt + (f4 << 2);
                CP_ASYNC16(smem_u32(dst), src);
            }
            CP_COMMIT();
            asm volatile("cp.async.wait_group 1;");   // tile ti complete
        } else {
            asm volatile("cp.async.wait_group 0;");
        }
        __syncthreads();   // x(ti) visible; also fences last tile's STG-s reads vs STS-u below

        // slide window by 32 (tile ti data in slot (ti+1)&1)
        if (ti > 0) {
            float f[32];
#pragma unroll
            for (int i = 0; i < 8; i++) {
                float4 a = *reinterpret_cast<const float4*>(
                    &xb[(((ti + 1) & 1) * 128 + tid) * TS + (i << 2)]);
                f[4 * i + 0] = a.x; f[4 * i + 1] = a.y; f[4 * i + 2] = a.z; f[4 * i + 3] = a.w;
            }
#pragma unroll
            for (int m = 0; m < 30; m++) xp[m] = xp[m + 32];
            PACK2(xp[30], xlast, f[0]);
#pragma unroll
            for (int i = 0; i < 31; i++) PACK2(xp[31 + i], f[i], f[i + 1]);
            xlast = f[31];
        }

        // conv: 4 quarters x 8 outputs (4 FFMA2 pairs); ascending j per channel
        // (bitwise-identical to validated conv: offsets 0 / 16 / 24)
#pragma unroll
        for (int q = 0; q < 4; q++) {
            unsigned long long A0[4], A1[4], A2[4];   // ch w8, w16, w32
#pragma unroll
            for (int p = 0; p < 4; p++) { A0[p] = 0ULL; A1[p] = 0ULL; A2[p] = 0ULL; }
            const int off = q << 3;
#pragma unroll
            for (int j = 0; j < 32; j++) {
                unsigned long long w2 = wb[j];
#pragma unroll
                for (int p = 0; p < 4; p++) FMA2(A2[p], xp[off + 2 * p + j], w2, A2[p]);
            }
#pragma unroll
            for (int j = 0; j < 16; j++) {
                unsigned long long w2 = wb[32 + j];
#pragma unroll
                for (int p = 0; p < 4; p++) FMA2(A1[p], xp[off + 2 * p + 16 + j], w2, A1[p]);
            }
#pragma unroll
            for (int j = 0; j < 8; j++) {
                unsigned long long w2 = wb[48 + j];
#pragma unroll
                for (int p = 0; p < 4; p++) FMA2(A0[p], xp[off + 2 * p + 24 + j], w2, A0[p]);
            }
#pragma unroll
            for (int p = 0; p < 4; p++) {
                int c = (q << 2) + p;                 // u64 column 0..15 (= t pair)
                ub64[(0 * 128 + tid) * 18 + c] = A0[p];
                ub64[(1 * 128 + tid) * 18 + c] = A1[p];
                ub64[(2 * 128 + tid) * 18 + c] = A2[p];
            }
        }
        __syncthreads();   // u tile complete in smem

        if (emit) {
            // coalesced u store: 3*128*8 = 3072 float4 tasks, 24 per thread
#pragma unroll
            for (int i = 0; i < 24; i++) {
                int p = tid + (i << 7);
                int k = p >> 10, row = (p >> 3) & 127, f4 = p & 7;
                float4 o = *reinterpret_cast<const float4*>(&ub[(k * 128 + row) * TS + (f4 << 2)]);
                *reinterpret_cast<float4*>(
                    uo + ((size_t)(b0 + row) * 3 + k) * TLEN + t0 + (f4 << 2)) = o;
            }
            __syncthreads();   // all u reads done before spikes overwrite
        }

        // LIF scan on own row; spikes written in place (emit only)
#pragma unroll
        for (int g = 0; g < 8; g++) {
            float4 c0 = *reinterpret_cast<const float4*>(&ub[(0 * 128 + tid) * TS + (g << 2)]);
            float4 c1 = *reinterpret_cast<const float4*>(&ub[(1 * 128 + tid) * TS + (g << 2)]);
            float4 c2 = *reinterpret_cast<const float4*>(&ub[(2 * 128 + tid) * TS + (g << 2)]);
            float4 o0, o1, o2;
            lif_step_s(c0.x, c1.x, c2.x, v0, v1, v2, o0.x, o1.x, o2.x);
            lif_step_s(c0.y, c1.y, c2.y, v0, v1, v2, o0.y, o1.y, o2.y);
            lif_step_s(c0.z, c1.z, c2.z, v0, v1, v2, o0.z, o1.z, o2.z);
            lif_step_s(c0.w, c1.w, c2.w, v0, v1, v2, o0.w, o1.w, o2.w);
            if (emit) {
                *reinterpret_cast<float4*>(&ub[(0 * 128 + tid) * TS + (g << 2)]) = o0;
                *reinterpret_cast<float4*>(&ub[(1 * 128 + tid) * TS + (g << 2)]) = o1;
                *reinterpret_cast<float4*>(&ub[(2 * 128 + tid) * TS + (g << 2)]) = o2;
            }
        }

        if (emit) {
            __syncthreads();   // spike tile complete
#pragma unroll
            for (int i = 0; i < 24; i++) {
                int p = tid + (i << 7);
                int k = p >> 10, row = (p >> 3) & 127, f4 = p & 7;
                float4 o = *reinterpret_cast<const float4*>(&ub[(k * 128 + row) * TS + (f4 << 2)]);
                *reinterpret_cast<float4*>(
                    so + ((size_t)(b0 + row) * 3 + k) * TLEN + t0 + (f4 << 2)) = o;
            }
        }
        // next iteration's post-wait __syncthreads orders these STG reads
        // before the next tile's STS-u writes.
    }
}

// ---------------------------------------------------------------------------
extern "C" void kernel_launch(void* const* d_in, const int* in_sizes, int n_in,
                              void* d_out, int out_size)
{
    const float* x   = (const float*)d_in[0];
    const float* w8  = (const float*)d_in[1];
    const float* w16 = (const float*)d_in[2];
    const float* w32 = (const float*)d_in[3];

    float* u = (float*)d_out;
    float* s = u + (size_t)BATCH * 3 * TLEN;

    const int SMEM = (112 + 2 * 128 * TS + 3 * 128 * TS) * 4;   // 92608 B
    static bool attr_set = false;
    if (!attr_set) {
        cudaFuncSetAttribute(fused_kernel,
            cudaFuncAttributeMaxDynamicSharedMemorySize, SMEM);
        attr_set = true;
    }

    fused_kernel<<<dim3(BATCH / ROWS_PB, NSEG), 128, SMEM>>>(x, w8, w16, w32, u, s);
}